// round 16
// baseline (speedup 1.0000x reference)
#include <cuda_runtime.h>
#include <cuda_bf16.h>
#include <cuda_fp16.h>
#include <math.h>
#include <stdint.h>

#define BB 32
#define TT 2048
#define HH 512
#define UU 32
#define ROWS (BB*TT)   // 65536

typedef unsigned int u32;

__device__ float g_sum[BB * HH];
// delta split: [row][u] bf16, hi + lo residual (4 MB each)
__device__ __align__(16) __nv_bfloat16 g_dhi[(size_t)ROWS * UU];
__device__ __align__(16) __nv_bfloat16 g_dlo[(size_t)ROWS * UU];
// fp16 exp-score cache [row][h] (64 MB)
__device__ __align__(16) __half g_e[(size_t)ROWS * HH];
// pre-split transposed weights: [tensor][u][k] bf16; 0=Wxh 1=Wxl 2=Wth 3=Wtl
__device__ __align__(16) __nv_bfloat16 g_wb[4][UU * HH];   // 128 KB
// pre-split transposed Wa: [h][u] bf16 (hi, lo)
__device__ __align__(16) __nv_bfloat16 g_wa[2][HH * UU];   // 64 KB

// ---------------- helpers ----------------
__device__ __forceinline__ float fast_tanh(float a) {
    return 1.0f - 2.0f / (__expf(2.0f * a) + 1.0f);
}
// split one float2 (consecutive k) into bf16x2 hi + bf16x2 lo (fragment-ready)
__device__ __forceinline__ void cvt2(float2 f, u32& hi, u32& lo) {
    __nv_bfloat162 h = __float22bfloat162_rn(f);
    const u32 hb = *reinterpret_cast<u32*>(&h);
    const float hx = __uint_as_float(hb << 16);
    const float hy = __uint_as_float(hb & 0xffff0000u);
    __nv_bfloat162 l = __float22bfloat162_rn(make_float2(f.x - hx, f.y - hy));
    hi = hb;
    lo = *reinterpret_cast<u32*>(&l);
}
__device__ __forceinline__ void ldm4(u32* r, u32 addr) {
    asm volatile("ldmatrix.sync.aligned.m8n8.x4.shared.b16 {%0,%1,%2,%3}, [%4];"
                 : "=r"(r[0]), "=r"(r[1]), "=r"(r[2]), "=r"(r[3]) : "r"(addr));
}
__device__ __forceinline__ void mma16816(float* d, const u32* a, const u32* b) {
    asm volatile(
        "mma.sync.aligned.m16n8k16.row.col.f32.bf16.bf16.f32 "
        "{%0,%1,%2,%3}, {%4,%5,%6,%7}, {%8,%9}, {%0,%1,%2,%3};"
        : "+f"(d[0]), "+f"(d[1]), "+f"(d[2]), "+f"(d[3])
        : "r"(a[0]), "r"(a[1]), "r"(a[2]), "r"(a[3]), "r"(b[0]), "r"(b[1]));
}
__device__ __forceinline__ float2 lds64(u32 addr) {
    float2 v;
    asm volatile("ld.shared.v2.f32 {%0,%1}, [%2];" : "=f"(v.x), "=f"(v.y) : "r"(addr));
    return v;
}
__device__ __forceinline__ void cp16(u32 dst, const void* src) {
    asm volatile("cp.async.cg.shared.global [%0], [%1], 16;" :: "r"(dst), "l"(src));
}
// W tile swizzle: [rows][64B], 16B slots
__device__ __forceinline__ u32 aoff(int row, int slot) {
    const int key = (row & 3) ^ ((row >> 2) & 1);
    return (u32)(row * 64 + ((slot ^ key) << 4));
}
// scores tile swizzle
__device__ __forceinline__ u32 soff(int r, int slot) {
    return (u32)(r * 64 + ((slot ^ ((r >> 1) & 3)) << 4));
}

// =====================================================================
// K0a/b/c: pre-split weights (3 launches so k_delta is launch #3 = ncu)
// =====================================================================
__global__ void k_prep_wx(const float* __restrict__ kx) {
    const int i = blockIdx.x * 256 + threadIdx.x;
    const int k = i >> 5, u = i & 31;
    const float w = kx[i];
    const __nv_bfloat16 h = __float2bfloat16_rn(w);
    g_wb[0][u * HH + k] = h;
    g_wb[1][u * HH + k] = __float2bfloat16_rn(w - __bfloat162float(h));
}
__global__ void k_prep_wt(const float* __restrict__ kt) {
    const int i = blockIdx.x * 256 + threadIdx.x;
    const int k = i >> 5, u = i & 31;
    const float w = kt[i];
    const __nv_bfloat16 h = __float2bfloat16_rn(w);
    g_wb[2][u * HH + k] = h;
    g_wb[3][u * HH + k] = __float2bfloat16_rn(w - __bfloat162float(h));
}
__global__ void k_prep_wa(const float* __restrict__ ka) {
    const int i = blockIdx.x * 256 + threadIdx.x;   // i = u*512 + h
    const int u = i >> 9, h = i & 511;
    const float w = ka[i];
    const __nv_bfloat16 hb = __float2bfloat16_rn(w);
    g_wa[0][h * UU + u] = hb;
    g_wa[1][h * UU + u] = __float2bfloat16_rn(w - __bfloat162float(hb));
}

// =====================================================================
// K1 (HMMA, cp.async pipelined): CTA = 128 rows, 8 warps (16 rows x 32 u).
// A staged f32 via cp.async (double-buffered, pad-160B rows: LDS conflict-
// free); W bf16 double-buffered in the proven aoff swizzle. kc = 32.
// 3-term bf16 split: ah@bh + ah@bl + al@bh. Depth-2 prefetch, no LDG chains.
// =====================================================================
#define DX0 0
#define DT0 40960
#define DW0 81920
#define D_SMEM 98304    // 2x20480 (x) + 2x20480 (t) + 2x8192 (W)

__global__ void __launch_bounds__(256, 2)
k_delta(const float* __restrict__ x, const float* __restrict__ t,
        const float* __restrict__ bx, const float* __restrict__ bt,
        const float* __restrict__ lambd)
{
    extern __shared__ char smem[];
    const u32 sb = (u32)__cvta_generic_to_shared(smem);
    const int tid = threadIdx.x;
    const int w = tid >> 5;
    const int lane = tid & 31;
    const int rowBase = blockIdx.x * 128;

    if (blockIdx.x < 64) g_sum[blockIdx.x * 256 + tid] = 0.0f;

    float accG[4][4], accB[4][4];
#pragma unroll
    for (int j = 0; j < 4; j++)
#pragma unroll
        for (int q = 0; q < 4; q++) { accG[j][q] = 0.0f; accB[j][q] = 0.0f; }

    auto stage = [&](int c, int buf) {
#pragma unroll
        for (int p = 0; p < 4; p++) {
            const int id = tid + 256 * p;         // 0..1023
            const int r = id >> 3, q = id & 7;
            const u32 d = (u32)(r * 160 + q * 16);
            const size_t go = (size_t)(rowBase + r) * HH + c * 32 + q * 4;
            cp16(sb + DX0 + buf * 20480 + d, x + go);
            cp16(sb + DT0 + buf * 20480 + d, t + go);
        }
#pragma unroll
        for (int p = 0; p < 2; p++) {
            const int id = tid + 256 * p;         // 0..511
            const int part = id >> 7, u = (id >> 2) & 31, sl = id & 3;
            cp16(sb + DW0 + buf * 8192 + part * 2048 + aoff(u, sl),
                 (const char*)g_wb[part] + u * 1024 + c * 64 + sl * 16);
        }
        asm volatile("cp.async.commit_group;" ::: "memory");
    };

    stage(0, 0);

    const u32 arow = (u32)((w * 16 + (lane >> 2)) * 160 + (lane & 3) * 8);
    const int bu = ((lane >> 4) & 1) * 8 + (lane & 7);
    const int bc0 = (lane >> 3) & 1;

    for (int c = 0; c < 16; c++) {
        if (c < 15) {
            stage(c + 1, (c + 1) & 1);
            asm volatile("cp.async.wait_group 1;" ::: "memory");
        } else {
            asm volatile("cp.async.wait_group 0;" ::: "memory");
        }
        __syncthreads();

        const u32 axb = sb + DX0 + (c & 1) * 20480 + arow;
        const u32 atb = sb + DT0 + (c & 1) * 20480 + arow;
        const u32 wb = sb + DW0 + (c & 1) * 8192;

#pragma unroll
        for (int s = 0; s < 2; s++) {
            const u32 ko = (u32)(s * 64);
            const u32 wb0 = aoff(bu, bc0 + 2 * s);
            const u32 wb1 = aoff(bu + 16, bc0 + 2 * s);

            u32 bh[8], bl[8], ah[4], al[4];
            // ---- gamma: x vs Wx ----
            ldm4(bh + 0, wb + 0 * 2048 + wb0);
            ldm4(bh + 4, wb + 0 * 2048 + wb1);
            ldm4(bl + 0, wb + 1 * 2048 + wb0);
            ldm4(bl + 4, wb + 1 * 2048 + wb1);
            {
                float2 f0 = lds64(axb + ko);
                float2 f1 = lds64(axb + ko + 1280);
                float2 f2 = lds64(axb + ko + 32);
                float2 f3 = lds64(axb + ko + 1280 + 32);
                cvt2(f0, ah[0], al[0]);
                cvt2(f1, ah[1], al[1]);
                cvt2(f2, ah[2], al[2]);
                cvt2(f3, ah[3], al[3]);
            }
#pragma unroll
            for (int j = 0; j < 4; j++) {
                mma16816(accG[j], ah, bh + 2 * j);
                mma16816(accG[j], ah, bl + 2 * j);
                mma16816(accG[j], al, bh + 2 * j);
            }
            // ---- beta: t vs Wt ----
            ldm4(bh + 0, wb + 2 * 2048 + wb0);
            ldm4(bh + 4, wb + 2 * 2048 + wb1);
            ldm4(bl + 0, wb + 3 * 2048 + wb0);
            ldm4(bl + 4, wb + 3 * 2048 + wb1);
            {
                float2 f0 = lds64(atb + ko);
                float2 f1 = lds64(atb + ko + 1280);
                float2 f2 = lds64(atb + ko + 32);
                float2 f3 = lds64(atb + ko + 1280 + 32);
                cvt2(f0, ah[0], al[0]);
                cvt2(f1, ah[1], al[1]);
                cvt2(f2, ah[2], al[2]);
                cvt2(f3, ah[3], al[3]);
            }
#pragma unroll
            for (int j = 0; j < 4; j++) {
                mma16816(accB[j], ah, bh + 2 * j);
                mma16816(accB[j], ah, bl + 2 * j);
                mma16816(accB[j], al, bh + 2 * j);
            }
        }
        __syncthreads();
    }

    // epilogue: bias + tanh + lambda combine -> g_dhi/g_dlo (bf16 split)
    const int rowL = rowBase + w * 16 + (lane >> 2);
    const int rowH = rowL + 8;
    const float lamL = __ldg(lambd + (rowL & (TT - 1)));
    const float lamH = __ldg(lambd + (rowH & (TT - 1)));
#pragma unroll
    for (int j = 0; j < 4; j++) {
        const int u0 = j * 8 + (lane & 3) * 2;
        const float bx0 = __ldg(bx + u0), bx1 = __ldg(bx + u0 + 1);
        const float bt0 = __ldg(bt + u0), bt1 = __ldg(bt + u0 + 1);
        float2 oL, oH;
        oL.x = lamL * fast_tanh(accG[j][0] + bx0) + (1.0f - lamL) * fast_tanh(accB[j][0] + bt0);
        oL.y = lamL * fast_tanh(accG[j][1] + bx1) + (1.0f - lamL) * fast_tanh(accB[j][1] + bt1);
        oH.x = lamH * fast_tanh(accG[j][2] + bx0) + (1.0f - lamH) * fast_tanh(accB[j][2] + bt0);
        oH.y = lamH * fast_tanh(accG[j][3] + bx1) + (1.0f - lamH) * fast_tanh(accB[j][3] + bt1);

        __nv_bfloat162 h2 = __float22bfloat162_rn(oL);
        float2 hf = __bfloat1622float2(h2);
        *(__nv_bfloat162*)(g_dhi + (size_t)rowL * UU + u0) = h2;
        *(__nv_bfloat162*)(g_dlo + (size_t)rowL * UU + u0) =
            __float22bfloat162_rn(make_float2(oL.x - hf.x, oL.y - hf.y));
        h2 = __float22bfloat162_rn(oH);
        hf = __bfloat1622float2(h2);
        *(__nv_bfloat162*)(g_dhi + (size_t)rowH * UU + u0) = h2;
        *(__nv_bfloat162*)(g_dlo + (size_t)rowH * UU + u0) =
            __float22bfloat162_rn(make_float2(oH.x - hf.x, oH.y - hf.y));
    }
}

// =====================================================================
// K2: scores GEMM once; e = exp(score) stored fp16 to g_e; sums -> g_sum.
// 512 threads, 16 warps (warp = 16 rows x 128 h), CTA = 64 rows.
// =====================================================================
#define K2S_BH 0
#define K2S_BL 32768
#define K2S_AH 65536
#define K2S_AL 69632
#define K2S_SUM 73728
#define K2_SMEM (K2S_SUM + HH*4)   // 75776

__global__ void __launch_bounds__(512, 1)
k_escore(int dummy) {
    extern __shared__ char smem[];
    const u32 sb = (u32)__cvta_generic_to_shared(smem);
    float* ssum = (float*)(smem + K2S_SUM);

    const int tid = threadIdx.x;
    const int lane = tid & 31;
    const int wid = tid >> 5;
    const int rowBase = blockIdx.x * 64;

    ssum[tid] = 0.0f;

#pragma unroll
    for (int p = 0; p < 4; p++) {
        const int i = tid + 512 * p;
        const int h = i >> 2, sl = i & 3;
        const u32 d = soff(h, sl);
        *(uint4*)(smem + K2S_BH + d) = *(const uint4*)((const char*)g_wa[0] + h * 64 + sl * 16);
        *(uint4*)(smem + K2S_BL + d) = *(const uint4*)((const char*)g_wa[1] + h * 64 + sl * 16);
    }
    {
        const int i = tid & 255;
        const int r = i >> 2, sl = i & 3;
        const u32 d = soff(r, sl);
        const size_t go = (size_t)(rowBase + r) * 64 + sl * 16;
        if (tid < 256)
            *(uint4*)(smem + K2S_AH + d) = *(const uint4*)((const char*)g_dhi + go);
        else
            *(uint4*)(smem + K2S_AL + d) = *(const uint4*)((const char*)g_dlo + go);
    }
    __syncthreads();

    const int g = lane >> 3, l = lane & 7;
    const int rt = wid & 3;
    const int hq = wid >> 2;

    float acc[16][4];
#pragma unroll
    for (int n = 0; n < 16; n++)
#pragma unroll
        for (int q = 0; q < 4; q++) acc[n][q] = 0.0f;

#pragma unroll
    for (int s = 0; s < 2; s++) {
        u32 ah[4], al[4];
        const u32 ao = soff(rt * 16 + (g & 1) * 8 + l, 2 * s + (g >> 1));
        ldm4(ah, sb + K2S_AH + ao);
        ldm4(al, sb + K2S_AL + ao);
#pragma unroll
        for (int nt = 0; nt < 8; nt++) {
            const int h0 = hq * 128 + nt * 16;
            const u32 bo = soff(h0 + (g >> 1) * 8 + l, 2 * s + (g & 1));
            u32 bh[4], bl[4];
            ldm4(bh, sb + K2S_BH + bo);
            ldm4(bl, sb + K2S_BL + bo);
            mma16816(acc[2 * nt],     ah, bh);
            mma16816(acc[2 * nt],     ah, bl);
            mma16816(acc[2 * nt],     al, bh);
            mma16816(acc[2 * nt + 1], ah, bh + 2);
            mma16816(acc[2 * nt + 1], ah, bl + 2);
            mma16816(acc[2 * nt + 1], al, bh + 2);
        }
    }

    const int rowL = rowBase + rt * 16 + (lane >> 2);
    __half* eL = g_e + (size_t)rowL * HH;
    __half* eH = eL + 8 * HH;
#pragma unroll
    for (int n8 = 0; n8 < 16; n8++) {
        const int h = hq * 128 + n8 * 8 + (lane & 3) * 2;
        const float e00 = __expf(acc[n8][0]), e01 = __expf(acc[n8][1]);
        const float e10 = __expf(acc[n8][2]), e11 = __expf(acc[n8][3]);
        *(__half2*)(eL + h) = __floats2half2_rn(e00, e01);
        *(__half2*)(eH + h) = __floats2half2_rn(e10, e11);
        float s0 = e00 + e10, s1 = e01 + e11;
        s0 += __shfl_xor_sync(0xffffffffu, s0, 4);
        s0 += __shfl_xor_sync(0xffffffffu, s0, 8);
        s0 += __shfl_xor_sync(0xffffffffu, s0, 16);
        s1 += __shfl_xor_sync(0xffffffffu, s1, 4);
        s1 += __shfl_xor_sync(0xffffffffu, s1, 8);
        s1 += __shfl_xor_sync(0xffffffffu, s1, 16);
        if (lane < 4) {
            atomicAdd(&ssum[h], s0);
            atomicAdd(&ssum[h + 1], s1);
        }
    }
    __syncthreads();

    const int b = blockIdx.x >> 5;
    atomicAdd(&g_sum[b * HH + tid], ssum[tid]);
}

// =====================================================================
// K3: alpha = fp16 e / sum — pure elementwise (read 67MB, write 134MB).
// Block = 8 rows (4096 elems = 512 8-half units) of one batch; 256 thr.
// =====================================================================
__global__ void __launch_bounds__(256)
k_norm(float* __restrict__ out) {
    __shared__ float sinv[HH];
    const int tid = threadIdx.x;
    const int b = blockIdx.x >> 8;          // 256 blocks per batch
    sinv[tid]       = 1.0f / g_sum[b * HH + tid];
    sinv[tid + 256] = 1.0f / g_sum[b * HH + tid + 256];
    __syncthreads();

    const uint4* e4 = (const uint4*)(g_e + (size_t)blockIdx.x * 4096);
    float4* o4 = (float4*)out + (size_t)blockIdx.x * 1024;
#pragma unroll
    for (int j = 0; j < 2; j++) {           // 512 units / 256 threads
        const int i8 = j * 256 + tid;       // 8-element unit, 0..511
        const uint4 hv = e4[i8];
        const int h0 = (i8 * 8) & (HH - 1);
        const float4 v0 = *(const float4*)(sinv + h0);
        const float4 v1 = *(const float4*)(sinv + h0 + 4);
        const float2 p0 = __half22float2(*(const __half2*)&hv.x);
        const float2 p1 = __half22float2(*(const __half2*)&hv.y);
        const float2 p2 = __half22float2(*(const __half2*)&hv.z);
        const float2 p3 = __half22float2(*(const __half2*)&hv.w);
        o4[2 * i8]     = make_float4(p0.x * v0.x, p0.y * v0.y, p1.x * v0.z, p1.y * v0.w);
        o4[2 * i8 + 1] = make_float4(p2.x * v1.x, p2.y * v1.y, p3.x * v1.z, p3.y * v1.w);
    }
}

// =====================================================================
extern "C" void kernel_launch(void* const* d_in, const int* in_sizes, int n_in,
                              void* d_out, int out_size) {
    const float* x     = (const float*)d_in[0];
    const float* t     = (const float*)d_in[1];
    const float* kx    = (const float*)d_in[2];
    const float* kt    = (const float*)d_in[3];
    const float* ka    = (const float*)d_in[4];
    const float* bx    = (const float*)d_in[5];
    const float* bt    = (const float*)d_in[6];
    const float* lambd = (const float*)d_in[7];
    float* out = (float*)d_out;

    cudaFuncSetAttribute(k_delta, cudaFuncAttributeMaxDynamicSharedMemorySize, D_SMEM);
    cudaFuncSetAttribute(k_escore, cudaFuncAttributeMaxDynamicSharedMemorySize, K2_SMEM);

    k_prep_wx<<<HH * UU / 256, 256>>>(kx);             // #0
    k_prep_wt<<<HH * UU / 256, 256>>>(kt);             // #1
    k_prep_wa<<<HH * UU / 256, 256>>>(ka);             // #2
    k_delta<<<ROWS / 128, 256, D_SMEM>>>(x, t, bx, bt, lambd);  // #3 <- ncu
    k_escore<<<ROWS / 64, 512, K2_SMEM>>>(0);          // #4
    k_norm<<<ROWS / 8, 256>>>(out);                    // #5
}

// round 17
// speedup vs baseline: 1.0269x; 1.0269x over previous
#include <cuda_runtime.h>
#include <cuda_bf16.h>
#include <cuda_fp16.h>
#include <math.h>
#include <stdint.h>

#define BB 32
#define TT 2048
#define HH 512
#define UU 32
#define ROWS (BB*TT)   // 65536

typedef unsigned int u32;

__device__ float g_sum[BB * HH];
// delta split: [row][u] bf16, hi + lo residual (4 MB each)
__device__ __align__(16) __nv_bfloat16 g_dhi[(size_t)ROWS * UU];
__device__ __align__(16) __nv_bfloat16 g_dlo[(size_t)ROWS * UU];
// fp16 exp-score cache [row][h] (64 MB)
__device__ __align__(16) __half g_e[(size_t)ROWS * HH];
// pre-split transposed weights: [tensor][u][k] bf16; 0=Wxh 1=Wxl 2=Wth 3=Wtl
__device__ __align__(16) __nv_bfloat16 g_wb[4][UU * HH];   // 128 KB
// pre-split transposed Wa: [h][u] bf16 (hi, lo)
__device__ __align__(16) __nv_bfloat16 g_wa[2][HH * UU];   // 64 KB

// ---------------- helpers ----------------
__device__ __forceinline__ float fast_tanh(float a) {
    return 1.0f - 2.0f / (__expf(2.0f * a) + 1.0f);
}
__device__ __forceinline__ void cvt2(float2 f, u32& hi, u32& lo) {
    __nv_bfloat162 h = __float22bfloat162_rn(f);
    const u32 hb = *reinterpret_cast<u32*>(&h);
    const float hx = __uint_as_float(hb << 16);
    const float hy = __uint_as_float(hb & 0xffff0000u);
    __nv_bfloat162 l = __float22bfloat162_rn(make_float2(f.x - hx, f.y - hy));
    hi = hb;
    lo = *reinterpret_cast<u32*>(&l);
}
__device__ __forceinline__ void ldm4(u32* r, u32 addr) {
    asm volatile("ldmatrix.sync.aligned.m8n8.x4.shared.b16 {%0,%1,%2,%3}, [%4];"
                 : "=r"(r[0]), "=r"(r[1]), "=r"(r[2]), "=r"(r[3]) : "r"(addr));
}
__device__ __forceinline__ void mma16816(float* d, const u32* a, const u32* b) {
    asm volatile(
        "mma.sync.aligned.m16n8k16.row.col.f32.bf16.bf16.f32 "
        "{%0,%1,%2,%3}, {%4,%5,%6,%7}, {%8,%9}, {%0,%1,%2,%3};"
        : "+f"(d[0]), "+f"(d[1]), "+f"(d[2]), "+f"(d[3])
        : "r"(a[0]), "r"(a[1]), "r"(a[2]), "r"(a[3]), "r"(b[0]), "r"(b[1]));
}
__device__ __forceinline__ float2 lds64(u32 addr) {
    float2 v;
    asm volatile("ld.shared.v2.f32 {%0,%1}, [%2];" : "=f"(v.x), "=f"(v.y) : "r"(addr));
    return v;
}
__device__ __forceinline__ void cp16(u32 dst, const void* src) {
    asm volatile("cp.async.cg.shared.global [%0], [%1], 16;" :: "r"(dst), "l"(src));
}
// W tile swizzle: [rows][64B], 16B slots
__device__ __forceinline__ u32 aoff(int row, int slot) {
    const int key = (row & 3) ^ ((row >> 2) & 1);
    return (u32)(row * 64 + ((slot ^ key) << 4));
}
// scores tile swizzle
__device__ __forceinline__ u32 soff(int r, int slot) {
    return (u32)(r * 64 + ((slot ^ ((r >> 1) & 3)) << 4));
}

// =====================================================================
// K0a/b/c: pre-split weights (3 launches so k_delta is launch #3 = ncu)
// =====================================================================
__global__ void k_prep_wx(const float* __restrict__ kx) {
    const int i = blockIdx.x * 256 + threadIdx.x;
    const int k = i >> 5, u = i & 31;
    const float w = kx[i];
    const __nv_bfloat16 h = __float2bfloat16_rn(w);
    g_wb[0][u * HH + k] = h;
    g_wb[1][u * HH + k] = __float2bfloat16_rn(w - __bfloat162float(h));
}
__global__ void k_prep_wt(const float* __restrict__ kt) {
    const int i = blockIdx.x * 256 + threadIdx.x;
    const int k = i >> 5, u = i & 31;
    const float w = kt[i];
    const __nv_bfloat16 h = __float2bfloat16_rn(w);
    g_wb[2][u * HH + k] = h;
    g_wb[3][u * HH + k] = __float2bfloat16_rn(w - __bfloat162float(h));
}
__global__ void k_prep_wa(const float* __restrict__ ka) {
    const int i = blockIdx.x * 256 + threadIdx.x;   // i = u*512 + h
    const int u = i >> 9, h = i & 511;
    const float w = ka[i];
    const __nv_bfloat16 hb = __float2bfloat16_rn(w);
    g_wa[0][h * UU + u] = hb;
    g_wa[1][h * UU + u] = __float2bfloat16_rn(w - __bfloat162float(hb));
}

// =====================================================================
// K1 (HMMA, cp.async pipelined) — unchanged from R16 (62.5us measured)
// =====================================================================
#define DX0 0
#define DT0 40960
#define DW0 81920
#define D_SMEM 98304

__global__ void __launch_bounds__(256, 2)
k_delta(const float* __restrict__ x, const float* __restrict__ t,
        const float* __restrict__ bx, const float* __restrict__ bt,
        const float* __restrict__ lambd)
{
    extern __shared__ char smem[];
    const u32 sb = (u32)__cvta_generic_to_shared(smem);
    const int tid = threadIdx.x;
    const int w = tid >> 5;
    const int lane = tid & 31;
    const int rowBase = blockIdx.x * 128;

    if (blockIdx.x < 64) g_sum[blockIdx.x * 256 + tid] = 0.0f;

    float accG[4][4], accB[4][4];
#pragma unroll
    for (int j = 0; j < 4; j++)
#pragma unroll
        for (int q = 0; q < 4; q++) { accG[j][q] = 0.0f; accB[j][q] = 0.0f; }

    auto stage = [&](int c, int buf) {
#pragma unroll
        for (int p = 0; p < 4; p++) {
            const int id = tid + 256 * p;
            const int r = id >> 3, q = id & 7;
            const u32 d = (u32)(r * 160 + q * 16);
            const size_t go = (size_t)(rowBase + r) * HH + c * 32 + q * 4;
            cp16(sb + DX0 + buf * 20480 + d, x + go);
            cp16(sb + DT0 + buf * 20480 + d, t + go);
        }
#pragma unroll
        for (int p = 0; p < 2; p++) {
            const int id = tid + 256 * p;
            const int part = id >> 7, u = (id >> 2) & 31, sl = id & 3;
            cp16(sb + DW0 + buf * 8192 + part * 2048 + aoff(u, sl),
                 (const char*)g_wb[part] + u * 1024 + c * 64 + sl * 16);
        }
        asm volatile("cp.async.commit_group;" ::: "memory");
    };

    stage(0, 0);

    const u32 arow = (u32)((w * 16 + (lane >> 2)) * 160 + (lane & 3) * 8);
    const int bu = ((lane >> 4) & 1) * 8 + (lane & 7);
    const int bc0 = (lane >> 3) & 1;

    for (int c = 0; c < 16; c++) {
        if (c < 15) {
            stage(c + 1, (c + 1) & 1);
            asm volatile("cp.async.wait_group 1;" ::: "memory");
        } else {
            asm volatile("cp.async.wait_group 0;" ::: "memory");
        }
        __syncthreads();

        const u32 axb = sb + DX0 + (c & 1) * 20480 + arow;
        const u32 atb = sb + DT0 + (c & 1) * 20480 + arow;
        const u32 wb = sb + DW0 + (c & 1) * 8192;

#pragma unroll
        for (int s = 0; s < 2; s++) {
            const u32 ko = (u32)(s * 64);
            const u32 wb0 = aoff(bu, bc0 + 2 * s);
            const u32 wb1 = aoff(bu + 16, bc0 + 2 * s);

            u32 bh[8], bl[8], ah[4], al[4];
            ldm4(bh + 0, wb + 0 * 2048 + wb0);
            ldm4(bh + 4, wb + 0 * 2048 + wb1);
            ldm4(bl + 0, wb + 1 * 2048 + wb0);
            ldm4(bl + 4, wb + 1 * 2048 + wb1);
            {
                float2 f0 = lds64(axb + ko);
                float2 f1 = lds64(axb + ko + 1280);
                float2 f2 = lds64(axb + ko + 32);
                float2 f3 = lds64(axb + ko + 1280 + 32);
                cvt2(f0, ah[0], al[0]);
                cvt2(f1, ah[1], al[1]);
                cvt2(f2, ah[2], al[2]);
                cvt2(f3, ah[3], al[3]);
            }
#pragma unroll
            for (int j = 0; j < 4; j++) {
                mma16816(accG[j], ah, bh + 2 * j);
                mma16816(accG[j], ah, bl + 2 * j);
                mma16816(accG[j], al, bh + 2 * j);
            }
            ldm4(bh + 0, wb + 2 * 2048 + wb0);
            ldm4(bh + 4, wb + 2 * 2048 + wb1);
            ldm4(bl + 0, wb + 3 * 2048 + wb0);
            ldm4(bl + 4, wb + 3 * 2048 + wb1);
            {
                float2 f0 = lds64(atb + ko);
                float2 f1 = lds64(atb + ko + 1280);
                float2 f2 = lds64(atb + ko + 32);
                float2 f3 = lds64(atb + ko + 1280 + 32);
                cvt2(f0, ah[0], al[0]);
                cvt2(f1, ah[1], al[1]);
                cvt2(f2, ah[2], al[2]);
                cvt2(f3, ah[3], al[3]);
            }
#pragma unroll
            for (int j = 0; j < 4; j++) {
                mma16816(accB[j], ah, bh + 2 * j);
                mma16816(accB[j], ah, bl + 2 * j);
                mma16816(accB[j], al, bh + 2 * j);
            }
        }
        __syncthreads();
    }

    const int rowL = rowBase + w * 16 + (lane >> 2);
    const int rowH = rowL + 8;
    const float lamL = __ldg(lambd + (rowL & (TT - 1)));
    const float lamH = __ldg(lambd + (rowH & (TT - 1)));
#pragma unroll
    for (int j = 0; j < 4; j++) {
        const int u0 = j * 8 + (lane & 3) * 2;
        const float bx0 = __ldg(bx + u0), bx1 = __ldg(bx + u0 + 1);
        const float bt0 = __ldg(bt + u0), bt1 = __ldg(bt + u0 + 1);
        float2 oL, oH;
        oL.x = lamL * fast_tanh(accG[j][0] + bx0) + (1.0f - lamL) * fast_tanh(accB[j][0] + bt0);
        oL.y = lamL * fast_tanh(accG[j][1] + bx1) + (1.0f - lamL) * fast_tanh(accB[j][1] + bt1);
        oH.x = lamH * fast_tanh(accG[j][2] + bx0) + (1.0f - lamH) * fast_tanh(accB[j][2] + bt0);
        oH.y = lamH * fast_tanh(accG[j][3] + bx1) + (1.0f - lamH) * fast_tanh(accB[j][3] + bt1);

        __nv_bfloat162 h2 = __float22bfloat162_rn(oL);
        float2 hf = __bfloat1622float2(h2);
        *(__nv_bfloat162*)(g_dhi + (size_t)rowL * UU + u0) = h2;
        *(__nv_bfloat162*)(g_dlo + (size_t)rowL * UU + u0) =
            __float22bfloat162_rn(make_float2(oL.x - hf.x, oL.y - hf.y));
        h2 = __float22bfloat162_rn(oH);
        hf = __bfloat1622float2(h2);
        *(__nv_bfloat162*)(g_dhi + (size_t)rowH * UU + u0) = h2;
        *(__nv_bfloat162*)(g_dlo + (size_t)rowH * UU + u0) =
            __float22bfloat162_rn(make_float2(oH.x - hf.x, oH.y - hf.y));
    }
}

// =====================================================================
// K2: scores GEMM; e = exp -> g_e (fp16); sums -> g_sum.
// 256 threads, blockIdx.y = h-half -> 2 CTAs/SM. CTA = 64 rows x 256 h.
// =====================================================================
#define E2_BH 0
#define E2_BL 16384
#define E2_AH 32768
#define E2_AL 36864
#define E2_SUM 40960
#define E2_SMEM (E2_SUM + 1024)   // 41984

__global__ void __launch_bounds__(256, 2)
k_escore(int dummy) {
    extern __shared__ char smem[];
    const u32 sb = (u32)__cvta_generic_to_shared(smem);
    float* ssum = (float*)(smem + E2_SUM);

    const int tid = threadIdx.x;
    const int lane = tid & 31;
    const int wid = tid >> 5;
    const int rowBase = blockIdx.x * 64;
    const int hy = blockIdx.y;              // h half: 0 or 1

    ssum[tid] = 0.0f;

    // stage B: this CTA's 256-h half of Wa (hi/lo), swizzled
#pragma unroll
    for (int p = 0; p < 4; p++) {
        const int i = tid + 256 * p;        // 0..1023
        const int h = i >> 2, sl = i & 3;   // local h 0..255
        const u32 d = soff(h, sl);
        *(uint4*)(smem + E2_BH + d) =
            *(const uint4*)((const char*)g_wa[0] + (hy * 256 + h) * 64 + sl * 16);
        *(uint4*)(smem + E2_BL + d) =
            *(const uint4*)((const char*)g_wa[1] + (hy * 256 + h) * 64 + sl * 16);
    }
    // stage A: 64 rows hi+lo
    {
        const int r = tid >> 2, sl = tid & 3;
        const u32 d = soff(r, sl);
        const size_t go = (size_t)(rowBase + r) * 64 + sl * 16;
        *(uint4*)(smem + E2_AH + d) = *(const uint4*)((const char*)g_dhi + go);
        *(uint4*)(smem + E2_AL + d) = *(const uint4*)((const char*)g_dlo + go);
    }
    __syncthreads();

    const int g = lane >> 3, l = lane & 7;
    const int rt = wid & 3;                 // row tile (16 rows)
    const int hq = wid >> 2;                // local h quarter (128 h)

    float acc[16][4];
#pragma unroll
    for (int n = 0; n < 16; n++)
#pragma unroll
        for (int q = 0; q < 4; q++) acc[n][q] = 0.0f;

#pragma unroll
    for (int s = 0; s < 2; s++) {
        u32 ah[4], al[4];
        const u32 ao = soff(rt * 16 + (g & 1) * 8 + l, 2 * s + (g >> 1));
        ldm4(ah, sb + E2_AH + ao);
        ldm4(al, sb + E2_AL + ao);
#pragma unroll
        for (int nt = 0; nt < 8; nt++) {
            const int h0 = hq * 128 + nt * 16;   // local h
            const u32 bo = soff(h0 + (g >> 1) * 8 + l, 2 * s + (g & 1));
            u32 bh[4], bl[4];
            ldm4(bh, sb + E2_BH + bo);
            ldm4(bl, sb + E2_BL + bo);
            mma16816(acc[2 * nt],     ah, bh);
            mma16816(acc[2 * nt],     ah, bl);
            mma16816(acc[2 * nt],     al, bh);
            mma16816(acc[2 * nt + 1], ah, bh + 2);
            mma16816(acc[2 * nt + 1], ah, bl + 2);
            mma16816(acc[2 * nt + 1], al, bh + 2);
        }
    }

    const int rowL = rowBase + rt * 16 + (lane >> 2);
    __half* eL = g_e + (size_t)rowL * HH + hy * 256;
    __half* eH = eL + 8 * HH;
#pragma unroll
    for (int n8 = 0; n8 < 16; n8++) {
        const int h = hq * 128 + n8 * 8 + (lane & 3) * 2;   // local h
        const float e00 = __expf(acc[n8][0]), e01 = __expf(acc[n8][1]);
        const float e10 = __expf(acc[n8][2]), e11 = __expf(acc[n8][3]);
        *(__half2*)(eL + h) = __floats2half2_rn(e00, e01);
        *(__half2*)(eH + h) = __floats2half2_rn(e10, e11);
        float s0 = e00 + e10, s1 = e01 + e11;
        s0 += __shfl_xor_sync(0xffffffffu, s0, 4);
        s0 += __shfl_xor_sync(0xffffffffu, s0, 8);
        s0 += __shfl_xor_sync(0xffffffffu, s0, 16);
        s1 += __shfl_xor_sync(0xffffffffu, s1, 4);
        s1 += __shfl_xor_sync(0xffffffffu, s1, 8);
        s1 += __shfl_xor_sync(0xffffffffu, s1, 16);
        if (lane < 4) {
            atomicAdd(&ssum[h], s0);
            atomicAdd(&ssum[h + 1], s1);
        }
    }
    __syncthreads();

    const int b = blockIdx.x >> 5;          // 32 row-blocks per batch
    atomicAdd(&g_sum[b * HH + hy * 256 + tid], ssum[tid]);
}

// =====================================================================
// K3: alpha = fp16 e / sum — pure elementwise. Block = 8 rows; 256 thr.
// =====================================================================
__global__ void __launch_bounds__(256)
k_norm(float* __restrict__ out) {
    __shared__ float sinv[HH];
    const int tid = threadIdx.x;
    const int b = blockIdx.x >> 8;          // 256 blocks per batch
    sinv[tid]       = 1.0f / g_sum[b * HH + tid];
    sinv[tid + 256] = 1.0f / g_sum[b * HH + tid + 256];
    __syncthreads();

    const uint4* e4 = (const uint4*)(g_e + (size_t)blockIdx.x * 4096);
    float4* o4 = (float4*)out + (size_t)blockIdx.x * 1024;
#pragma unroll
    for (int j = 0; j < 2; j++) {           // 512 units / 256 threads
        const int i8 = j * 256 + tid;
        const uint4 hv = e4[i8];
        const int h0 = (i8 * 8) & (HH - 1);
        const float4 v0 = *(const float4*)(sinv + h0);
        const float4 v1 = *(const float4*)(sinv + h0 + 4);
        const float2 p0 = __half22float2(*(const __half2*)&hv.x);
        const float2 p1 = __half22float2(*(const __half2*)&hv.y);
        const float2 p2 = __half22float2(*(const __half2*)&hv.z);
        const float2 p3 = __half22float2(*(const __half2*)&hv.w);
        o4[2 * i8]     = make_float4(p0.x * v0.x, p0.y * v0.y, p1.x * v0.z, p1.y * v0.w);
        o4[2 * i8 + 1] = make_float4(p2.x * v1.x, p2.y * v1.y, p3.x * v1.z, p3.y * v1.w);
    }
}

// =====================================================================
extern "C" void kernel_launch(void* const* d_in, const int* in_sizes, int n_in,
                              void* d_out, int out_size) {
    const float* x     = (const float*)d_in[0];
    const float* t     = (const float*)d_in[1];
    const float* kx    = (const float*)d_in[2];
    const float* kt    = (const float*)d_in[3];
    const float* ka    = (const float*)d_in[4];
    const float* bx    = (const float*)d_in[5];
    const float* bt    = (const float*)d_in[6];
    const float* lambd = (const float*)d_in[7];
    float* out = (float*)d_out;

    cudaFuncSetAttribute(k_delta, cudaFuncAttributeMaxDynamicSharedMemorySize, D_SMEM);
    cudaFuncSetAttribute(k_escore, cudaFuncAttributeMaxDynamicSharedMemorySize, E2_SMEM);

    k_prep_wx<<<HH * UU / 256, 256>>>(kx);             // #0
    k_prep_wt<<<HH * UU / 256, 256>>>(kt);             // #1
    k_prep_wa<<<HH * UU / 256, 256>>>(ka);             // #2
    k_delta<<<ROWS / 128, 256, D_SMEM>>>(x, t, bx, bt, lambd);  // #3 <- ncu
    k_escore<<<dim3(ROWS / 64, 2), 256, E2_SMEM>>>(0); // #4
    k_norm<<<ROWS / 8, 256>>>(out);                    // #5
}